// round 12
// baseline (speedup 1.0000x reference)
#include <cuda_runtime.h>
#include <cstdint>

#define MAXB 8
#define JT 128
#define SPLIT 2
#define JH (JT / SPLIT)
#define JG (JH / 2)          // packed j-groups per block
#define MAXTILES 40
#define MAXTRI (MAXTILES * (MAXTILES + 1) / 2)   // 820

// ---------------- scratch (device globals; no allocation) ----------------
__device__ float  g_mom_part[MAXB][MAXTILES][18];       // per-diagonal-tile moment partials
__device__ float  g_cross_part[MAXB * MAXTRI * SPLIT];  // per-block bond cross partials
__device__ float  g_pts_part[MAXB * 64];                // per-chunk point-loss partials
__device__ double g_Sw[MAXB];
__device__ double g_analytic[MAXB];
__device__ float  g_R[MAXB][9];
__device__ float  g_mup[MAXB][3];
__device__ float  g_mug[MAXB][3];
__device__ int    g_count1 = 0;    // phase-1 completion counter (self-resetting)
__device__ int    g_count2 = 0;    // pts completion counter (self-resetting)
__device__ int    g_flag   = 0;    // solve-done flag (self-resetting)

// ---- packed f32x2 helpers (sm_103a FFMA2 path) ----
#define FMA2(d, a, b, c) asm("fma.rn.f32x2 %0, %1, %2, %3;" : "=l"(d) : "l"(a), "l"(b), "l"(c))
#define ADD2(d, a, b)    asm("add.rn.f32x2 %0, %1, %2;"     : "=l"(d) : "l"(a), "l"(b))
#define MUL2(d, a, b)    asm("mul.rn.f32x2 %0, %1, %2;"     : "=l"(d) : "l"(a), "l"(b))

__device__ __forceinline__ unsigned long long packf2(float lo, float hi) {
    unsigned long long r;
    asm("mov.b64 %0, {%1, %2};" : "=l"(r) : "f"(lo), "f"(hi));
    return r;
}
__device__ __forceinline__ void unpackf2(float& lo, float& hi, unsigned long long v) {
    asm("mov.b64 {%0, %1}, %2;" : "=f"(lo), "=f"(hi) : "l"(v));
}

__device__ __forceinline__ float fsqrt_fast(float x) {
    float r; asm("sqrt.approx.f32 %0, %1;" : "=f"(r) : "f"(x)); return r;
}

__device__ __forceinline__ float block_reduce_f(float v) {
    #pragma unroll
    for (int o = 16; o > 0; o >>= 1) v += __shfl_down_sync(0xffffffffu, v, o);
    __shared__ float s[32];
    int lane = threadIdx.x & 31, wid = threadIdx.x >> 5;
    if (lane == 0) s[wid] = v;
    __syncthreads();
    int nw = (blockDim.x + 31) >> 5;
    v = (threadIdx.x < nw) ? s[threadIdx.x] : 0.0f;
    if (wid == 0) {
        #pragma unroll
        for (int o = 16; o > 0; o >>= 1) v += __shfl_down_sync(0xffffffffu, v, o);
    }
    return v;  // valid in thread 0
}

// ================= SINGLE FUSED KERNEL =================
// Phase 1 (all blocks): bond cross tiles (+ moments on diagonal tiles).
// Phase 2 (last phase-1 block): moment combine + Kabsch solve, release flag.
// Phase 3 (blocks with flat id < chunks): point loss; last one does final combine.
// Progress guarantee: only <=64 blocks ever spin; >=1184 SM block slots exist,
// so remaining phase-1 blocks always have slots to run; the flag is released
// only after ALL phase-1 blocks complete.
__global__ void __launch_bounds__(JT, 8) fused_kernel(
        const float* __restrict__ p, const float* __restrict__ gt,
        const float* __restrict__ w, const float* __restrict__ ht,
        float* __restrict__ out,
        int N, int B, int ntri, int tiles, int nblocks, int chunks, int cpb, int outn) {
    // packed-lane shared: group g covers j-pair (2g, 2g+1)
    __shared__ ulonglong2 shPa[JG];           // (px2, py2)   lanes = -2*p
    __shared__ ulonglong2 shPb[JG];           // (pz2, pw2)   pw = |p|^2
    __shared__ ulonglong2 shGa[JG];           // (gx2, gy2)   lanes = -2*g
    __shared__ ulonglong2 shGb[JG];           // (gz2, gw2)   gw = |g|^2
    __shared__ unsigned long long shw[JG];    // (w0, w1)
    __shared__ float smom[4][18];
    __shared__ int   sLast;

    int b   = blockIdx.z;
    int sub = blockIdx.y;
    int k   = blockIdx.x;
    int tid = threadIdx.x;
    // decode triangular index (k uniform per block)
    int ti = (int)((__fsqrt_rn(8.0f * (float)k + 1.0f) - 1.0f) * 0.5f);
    while ((ti + 1) * (ti + 2) / 2 <= k) ti++;
    while (ti * (ti + 1) / 2 > k) ti--;
    int tj = k - ti * (ti + 1) / 2;

    const size_t base = (size_t)b * N;

    // ---- stage the 64-j half-tile as packed lanes (3 thread groups of 32) ----
    {
        int grp = tid & 31;
        int j0 = tj * JT + sub * JH + 2 * grp;
        int j1 = j0 + 1;
        if (tid < 32) {
            float x0 = 0.f, y0 = 0.f, z0 = 0.f, x1 = 0.f, y1 = 0.f, z1 = 0.f;
            if (j0 < N) { const float* q = p + (base + j0) * 3; x0 = q[0]; y0 = q[1]; z0 = q[2]; }
            if (j1 < N) { const float* q = p + (base + j1) * 3; x1 = q[0]; y1 = q[1]; z1 = q[2]; }
            float n0 = fmaf(x0, x0, fmaf(y0, y0, z0 * z0));
            float n1 = fmaf(x1, x1, fmaf(y1, y1, z1 * z1));
            shPa[grp] = make_ulonglong2(packf2(-2.f * x0, -2.f * x1),
                                        packf2(-2.f * y0, -2.f * y1));
            shPb[grp] = make_ulonglong2(packf2(-2.f * z0, -2.f * z1),
                                        packf2(n0, n1));
        } else if (tid < 64) {
            float x0 = 0.f, y0 = 0.f, z0 = 0.f, x1 = 0.f, y1 = 0.f, z1 = 0.f;
            if (j0 < N) { const float* q = gt + (base + j0) * 3; x0 = q[0]; y0 = q[1]; z0 = q[2]; }
            if (j1 < N) { const float* q = gt + (base + j1) * 3; x1 = q[0]; y1 = q[1]; z1 = q[2]; }
            float n0 = fmaf(x0, x0, fmaf(y0, y0, z0 * z0));
            float n1 = fmaf(x1, x1, fmaf(y1, y1, z1 * z1));
            shGa[grp] = make_ulonglong2(packf2(-2.f * x0, -2.f * x1),
                                        packf2(-2.f * y0, -2.f * y1));
            shGb[grp] = make_ulonglong2(packf2(-2.f * z0, -2.f * z1),
                                        packf2(n0, n1));
        } else if (tid < 96) {
            float w0 = (j0 < N) ? w[base + j0] : 0.f;   // w=0 -> no contribution
            float w1 = (j1 < N) ? w[base + j1] : 0.f;
            shw[grp] = packf2(w0, w1);
        }
    }

    int i = ti * JT + tid;
    float xi = 0.f, yi = 0.f, zi = 0.f, gxi = 0.f, gyi = 0.f, gzi = 0.f, wi = 0.f;
    if (i < N) {
        const float* pi = p  + (base + i) * 3;
        const float* gi = gt + (base + i) * 3;
        xi = pi[0]; yi = pi[1]; zi = pi[2];
        gxi = gi[0]; gyi = gi[1]; gzi = gi[2];
        wi = w[base + i];
    }
    float spi = fmaf(xi, xi, fmaf(yi, yi, zi * zi));
    float sgi = fmaf(gxi, gxi, fmaf(gyi, gyi, gzi * gzi));

    // broadcast i-point into packed lanes
    unsigned long long xi2  = packf2(xi, xi),   yi2  = packf2(yi, yi),   zi2  = packf2(zi, zi);
    unsigned long long gxi2 = packf2(gxi, gxi), gyi2 = packf2(gyi, gyi), gzi2 = packf2(gzi, gzi);
    unsigned long long spi2 = packf2(spi, spi), sgi2 = packf2(sgi, sgi);
    __syncthreads();

    unsigned long long acc2 = 0ULL;
    #pragma unroll 8
    for (int jj = 0; jj < JG; jj++) {
        ulonglong2 Pa = shPa[jj];
        ulonglong2 Pb = shPb[jj];
        unsigned long long t;
        ADD2(t, spi2, Pb.y);          // spi + |pj|^2   (both lanes)
        FMA2(t, Pa.x, xi2, t);        // -2 px*xi
        FMA2(t, Pa.y, yi2, t);
        FMA2(t, Pb.x, zi2, t);        // t = dp^2 pair
        ulonglong2 Ga = shGa[jj];
        ulonglong2 Gb = shGb[jj];
        unsigned long long u;
        ADD2(u, sgi2, Gb.y);
        FMA2(u, Ga.x, gxi2, u);
        FMA2(u, Ga.y, gyi2, u);
        FMA2(u, Gb.x, gzi2, u);       // u = dg^2 pair
        unsigned long long prod;
        MUL2(prod, t, u);
        float p0, p1;
        unpackf2(p0, p1, prod);
        float s0 = fsqrt_fast(fmaxf(p0, 0.f));   // dp*dg with ONE sqrt per pair
        float s1 = fsqrt_fast(fmaxf(p1, 0.f));
        unsigned long long s2 = packf2(s0, s1);
        FMA2(acc2, shw[jj], s2, acc2);
    }
    float a0, a1;
    unpackf2(a0, a1, acc2);
    float factor = (ti == tj) ? 1.0f : 2.0f;
    float acc = (a0 + a1) * (wi * factor);

    float tot = block_reduce_f(acc);
    if (tid == 0) g_cross_part[(b * ntri + k) * SPLIT + sub] = tot;

    // Diagonal tiles (one split only) also compute the 18 weighted moments for
    // their i-range (one point per thread, already resident in registers).
    if (ti == tj && sub == 0) {
        float m[18];
        float wpx = wi * xi, wpy = wi * yi, wpz = wi * zi;
        m[0]  = wi;
        m[1]  = wpx; m[2]  = wpy; m[3]  = wpz;
        m[4]  = wi * gxi; m[5]  = wi * gyi; m[6]  = wi * gzi;
        m[7]  = wpx * gxi; m[8]  = wpx * gyi; m[9]  = wpx * gzi;
        m[10] = wpy * gxi; m[11] = wpy * gyi; m[12] = wpy * gzi;
        m[13] = wpz * gxi; m[14] = wpz * gyi; m[15] = wpz * gzi;
        m[16] = wi * spi;
        m[17] = wi * sgi;

        #pragma unroll
        for (int kk = 0; kk < 18; kk++) {
            #pragma unroll
            for (int o = 16; o > 0; o >>= 1)
                m[kk] += __shfl_down_sync(0xffffffffu, m[kk], o);
        }
        int lane = tid & 31, wd = tid >> 5;
        if (lane == 0) {
            #pragma unroll
            for (int kk = 0; kk < 18; kk++) smom[wd][kk] = m[kk];
        }
        __syncthreads();
        if (tid < 18)
            g_mom_part[b][ti][tid] =
                smom[0][tid] + smom[1][tid] + smom[2][tid] + smom[3][tid];
    }

    // ---- phase-1 completion barrier (arrival only) ----
    __syncthreads();
    if (tid == 0) {
        __threadfence();
        int old = atomicAdd(&g_count1, 1);
        sLast = (old == nblocks - 1) ? 1 : 0;
    }
    __syncthreads();

    // ================= Phase 2: solve (last phase-1 block only) =================
    if (sLast) {
        __shared__ double S[MAXB][18];
        if (tid < B * 18) {
            int bb = tid / 18, kk = tid % 18;
            double v = 0.0;
            for (int tt = 0; tt < tiles; tt++) v += (double)g_mom_part[bb][tt][kk];
            S[bb][kk] = v;
        }
        __syncthreads();

        if (tid < B) {
            int bb = tid;
            double Sw = S[bb][0];
            double invSw = 1.0 / Sw;
            double sp[3] = { S[bb][1], S[bb][2], S[bb][3] };
            double sg[3] = { S[bb][4], S[bb][5], S[bb][6] };

            double Md[3][3];
            #pragma unroll
            for (int ii = 0; ii < 3; ii++)
                #pragma unroll
                for (int jj = 0; jj < 3; jj++)
                    Md[ii][jj] = S[bb][7 + ii * 3 + jj] - sp[ii] * sg[jj] * invSw;

            double mx = 0.0;
            #pragma unroll
            for (int ii = 0; ii < 3; ii++)
                #pragma unroll
                for (int jj = 0; jj < 3; jj++)
                    mx = fmax(mx, fabs(Md[ii][jj]));
            double invmx = (mx > 0.0) ? 1.0 / mx : 0.0;

            float M[3][3];
            #pragma unroll
            for (int ii = 0; ii < 3; ii++)
                #pragma unroll
                for (int jj = 0; jj < 3; jj++)
                    M[ii][jj] = (float)(Md[ii][jj] * invmx);

            float A[3][3];
            #pragma unroll
            for (int ii = 0; ii < 3; ii++)
                #pragma unroll
                for (int jj = 0; jj < 3; jj++)
                    A[ii][jj] = M[0][ii] * M[0][jj] + M[1][ii] * M[1][jj] + M[2][ii] * M[2][jj];

            float V[3][3] = {{1, 0, 0}, {0, 1, 0}, {0, 0, 1}};

            for (int sweep = 0; sweep < 10; sweep++) {
                #pragma unroll
                for (int pair = 0; pair < 3; pair++) {
                    int pp = (pair == 2) ? 1 : 0;
                    int qq = (pair == 0) ? 1 : 2;
                    float apq = A[pp][qq];
                    if (fabsf(apq) < 1e-20f) continue;
                    float theta = (A[qq][qq] - A[pp][pp]) / (2.0f * apq);
                    float tt2 = ((theta >= 0.0f) ? 1.0f : -1.0f) /
                                (fabsf(theta) + fsqrt_fast(fmaf(theta, theta, 1.0f)));
                    float c = rsqrtf(fmaf(tt2, tt2, 1.0f));
                    float s = tt2 * c;
                    float app = A[pp][pp], aq2 = A[qq][qq];
                    A[pp][pp] = app - tt2 * apq;
                    A[qq][qq] = aq2 + tt2 * apq;
                    A[pp][qq] = A[qq][pp] = 0.0f;
                    int r = 3 - pp - qq;
                    float arp = A[r][pp], arq = A[r][qq];
                    A[r][pp] = A[pp][r] = c * arp - s * arq;
                    A[r][qq] = A[qq][r] = s * arp + c * arq;
                    #pragma unroll
                    for (int kk = 0; kk < 3; kk++) {
                        float vkp = V[kk][pp], vkq = V[kk][qq];
                        V[kk][pp] = c * vkp - s * vkq;
                        V[kk][qq] = s * vkp + c * vkq;
                    }
                }
            }

            float lam[3] = { A[0][0], A[1][1], A[2][2] };
            int id[3] = {0, 1, 2};
            if (lam[id[0]] < lam[id[1]]) { int x = id[0]; id[0] = id[1]; id[1] = x; }
            if (lam[id[0]] < lam[id[2]]) { int x = id[0]; id[0] = id[2]; id[2] = x; }
            if (lam[id[1]] < lam[id[2]]) { int x = id[1]; id[1] = id[2]; id[2] = x; }

            // U columns: u_k = normalize(M v_k), k=0,1; u_2 = u_0 x u_1 (det flip absorbed)
            float U[3][3];
            #pragma unroll
            for (int kk = 0; kk < 2; kk++) {
                float v0 = V[0][id[kk]], v1 = V[1][id[kk]], v2 = V[2][id[kk]];
                float u0 = M[0][0] * v0 + M[0][1] * v1 + M[0][2] * v2;
                float u1 = M[1][0] * v0 + M[1][1] * v1 + M[1][2] * v2;
                float u2 = M[2][0] * v0 + M[2][1] * v1 + M[2][2] * v2;
                float inv = rsqrtf(fmaxf(u0 * u0 + u1 * u1 + u2 * u2, 1e-30f));
                U[0][kk] = u0 * inv; U[1][kk] = u1 * inv; U[2][kk] = u2 * inv;
            }
            U[0][2] = U[1][0] * U[2][1] - U[2][0] * U[1][1];
            U[1][2] = U[2][0] * U[0][1] - U[0][0] * U[2][1];
            U[2][2] = U[0][0] * U[1][1] - U[1][0] * U[0][1];

            #pragma unroll
            for (int ii = 0; ii < 3; ii++)
                #pragma unroll
                for (int jj = 0; jj < 3; jj++)
                    g_R[bb][ii * 3 + jj] = U[ii][0] * V[jj][id[0]] + U[ii][1] * V[jj][id[1]]
                                         + U[ii][2] * V[jj][id[2]];

            #pragma unroll
            for (int ii = 0; ii < 3; ii++) {
                g_mup[bb][ii] = (float)(sp[ii] * invSw);
                g_mug[bb][ii] = (float)(sg[ii] * invSw);
            }

            g_Sw[bb] = Sw;
            g_analytic[bb] = 2.0 * Sw * (S[bb][16] + S[bb][17])
                           - 2.0 * (sp[0] * sp[0] + sp[1] * sp[1] + sp[2] * sp[2]
                                  + sg[0] * sg[0] + sg[1] * sg[1] + sg[2] * sg[2]);
        }
        __syncthreads();
        if (tid == 0) {
            __threadfence();
            atomicExch(&g_flag, 1);    // release: solve results visible
        }
    }

    // ================= Phase 3: point loss + final combine =================
    int fid = blockIdx.x + gridDim.x * (blockIdx.y + gridDim.y * blockIdx.z);
    if (fid >= chunks) return;        // non-pts blocks exit (never spin)

    if (!sLast) {
        if (tid == 0) {
            while (atomicAdd(&g_flag, 0) == 0) __nanosleep(64);
        }
        __syncthreads();
        __threadfence();
    }

    int pb_ = fid / cpb;
    int i0  = (fid % cpb) * JT;
    {
        const size_t pbase = (size_t)pb_ * N;
        float r00 = g_R[pb_][0], r01 = g_R[pb_][1], r02 = g_R[pb_][2];
        float r10 = g_R[pb_][3], r11 = g_R[pb_][4], r12 = g_R[pb_][5];
        float r20 = g_R[pb_][6], r21 = g_R[pb_][7], r22 = g_R[pb_][8];
        float m0 = g_mup[pb_][0], m1 = g_mup[pb_][1], m2 = g_mup[pb_][2];
        float u0 = g_mug[pb_][0], u1 = g_mug[pb_][1], u2 = g_mug[pb_][2];

        float acc3 = 0.0f;
        int ii = i0 + tid;
        if (ii < N) {
            const float* gb2 = gt + (pbase + ii) * 3;
            const float* pb2 = p  + (pbase + ii) * 3;
            float gx = gb2[0] - u0;
            float gy = gb2[1] - u1;
            float gz = gb2[2] - u2;
            float ax = fmaf(r00, gx, fmaf(r01, gy, r02 * gz)) + m0;
            float ay = fmaf(r10, gx, fmaf(r11, gy, r12 * gz)) + m1;
            float az = fmaf(r20, gx, fmaf(r21, gy, r22 * gz)) + m2;
            float dx = pb2[0] - ax;
            float dy = pb2[1] - ay;
            float dz = pb2[2] - az;
            float nsq = fmaf(dx, dx, fmaf(dy, dy, dz * dz));
            acc3 = w[pbase + ii] * fsqrt_fast(nsq);
        }
        __syncthreads();                // protect block_reduce_f scratch reuse
        float tot3 = block_reduce_f(acc3);

        __shared__ int sLast2;
        if (tid == 0) {
            g_pts_part[fid] = tot3;
            __threadfence();
            int old = atomicAdd(&g_count2, 1);
            sLast2 = (old == chunks - 1) ? 1 : 0;
        }
        __syncthreads();
        if (!sLast2) return;

        // ---- final combine (exactly one block; fixed summation order) ----
        int ncross = nblocks;
        double vp = 0.0, vc = 0.0;
        for (int idx = tid; idx < chunks; idx += JT) vp += (double)g_pts_part[idx];
        for (int idx = tid; idx < ncross; idx += JT) vc += (double)g_cross_part[idx];

        __shared__ double rp[JT];
        __shared__ double rc[JT];
        rp[tid] = vp;
        rc[tid] = vc;
        __syncthreads();
        for (int off = JT / 2; off > 0; off >>= 1) {
            if (tid < off) {
                rp[tid] += rp[tid + off];
                rc[tid] += rc[tid + off];
            }
            __syncthreads();
        }

        __shared__ double loss_sh;
        if (tid == 0) {
            double totW = 0.0, den = 0.0, an = 0.0;
            for (int bb = 0; bb < B; bb++) {
                double s = g_Sw[bb];
                totW += s;
                den  += s * s;
                an   += g_analytic[bb];
            }
            double loss_pts  = rp[0] / totW;
            double loss_bond = (an - 2.0 * rc[0]) / den;
            loss_sh = loss_pts + 1.0 * loss_bond;   // ALPHA_BOND = 1
            // self-reset for next graph replay
            g_count1 = 0;
            g_count2 = 0;
            g_flag   = 0;
        }
        __syncthreads();
        int bb = tid;
        if (bb < outn && bb < B) {
            double h = (double)ht[bb];
            out[bb] = (float)((h * h + 256.0) / ((h + 16.0) * (h + 16.0)) * loss_sh);
        }
    }
}

// ---------------- launcher ----------------
extern "C" void kernel_launch(void* const* d_in, const int* in_sizes, int n_in,
                              void* d_out, int out_size) {
    const float* p  = (const float*)d_in[0];  // xpred_l [B,N,3]
    const float* g  = (const float*)d_in[1];  // xGT_l   [B,N,3]
    const float* ht = (const float*)d_in[2];  // ht      [B]
    const float* w  = (const float*)d_in[3];  // w_l     [B,N]

    int B = in_sizes[2];
    if (B > MAXB) B = MAXB;
    int N = in_sizes[3] / B;

    int tiles = (N + JT - 1) / JT;
    if (tiles > MAXTILES) tiles = MAXTILES;   // (inputs are B=4, N=2048 -> 16 tiles)
    int ntri = tiles * (tiles + 1) / 2;
    int nblocks = ntri * SPLIT * B;
    int cpb = (N + JT - 1) / JT;
    int chunks = B * cpb;

    fused_kernel<<<dim3(ntri, SPLIT, B), JT>>>(p, g, w, ht, (float*)d_out,
                                               N, B, ntri, tiles, nblocks,
                                               chunks, cpb, out_size);
}

// round 13
// speedup vs baseline: 1.0156x; 1.0156x over previous
#include <cuda_runtime.h>
#include <cstdint>

#define MAXB 8
#define JT 128
#define SPLIT 2
#define JH (JT / SPLIT)
#define JG (JH / 2)          // packed j-groups per block
#define MAXTILES 40
#define MAXTRI (MAXTILES * (MAXTILES + 1) / 2)   // 820

// ---------------- scratch (device globals; no allocation) ----------------
__device__ float  g_mom_part[MAXB][MAXTILES][18];       // per-diagonal-tile moment partials
__device__ float  g_cross_part[MAXB * MAXTRI * SPLIT];  // per-block bond cross partials
__device__ float  g_pts_part[MAXB * MAXTILES];          // per-chunk point-loss partials
__device__ double g_Sw[MAXB];
__device__ double g_analytic[MAXB];
__device__ float  g_R[MAXB][9];
__device__ float  g_mup[MAXB][3];
__device__ float  g_mug[MAXB][3];
__device__ int    g_count1 = 0;    // phase-1 completion counter (self-resetting)
__device__ int    g_count2 = 0;    // pts completion counter (self-resetting)
__device__ int    g_flag   = 0;    // solve-done flag (self-resetting)

// ---- packed f32x2 helpers (sm_103a FFMA2 path) ----
#define FMA2(d, a, b, c) asm("fma.rn.f32x2 %0, %1, %2, %3;" : "=l"(d) : "l"(a), "l"(b), "l"(c))
#define ADD2(d, a, b)    asm("add.rn.f32x2 %0, %1, %2;"     : "=l"(d) : "l"(a), "l"(b))
#define MUL2(d, a, b)    asm("mul.rn.f32x2 %0, %1, %2;"     : "=l"(d) : "l"(a), "l"(b))

__device__ __forceinline__ unsigned long long packf2(float lo, float hi) {
    unsigned long long r;
    asm("mov.b64 %0, {%1, %2};" : "=l"(r) : "f"(lo), "f"(hi));
    return r;
}
__device__ __forceinline__ void unpackf2(float& lo, float& hi, unsigned long long v) {
    asm("mov.b64 {%0, %1}, %2;" : "=f"(lo), "=f"(hi) : "l"(v));
}

__device__ __forceinline__ float fsqrt_fast(float x) {
    float r; asm("sqrt.approx.f32 %0, %1;" : "=f"(r) : "f"(x)); return r;
}

__device__ __forceinline__ float block_reduce_f(float v) {
    #pragma unroll
    for (int o = 16; o > 0; o >>= 1) v += __shfl_down_sync(0xffffffffu, v, o);
    __shared__ float s[32];
    int lane = threadIdx.x & 31, wid = threadIdx.x >> 5;
    if (lane == 0) s[wid] = v;
    __syncthreads();
    int nw = (blockDim.x + 31) >> 5;
    v = (threadIdx.x < nw) ? s[threadIdx.x] : 0.0f;
    if (wid == 0) {
        #pragma unroll
        for (int o = 16; o > 0; o >>= 1) v += __shfl_down_sync(0xffffffffu, v, o);
    }
    return v;  // valid in thread 0
}

// ============ Phase 2: moment combine + Kabsch solve (COLD PATH, noinline) ============
__device__ __noinline__ void solve_phase(int B, int tiles) {
    __shared__ double S[MAXB][18];
    int tid = threadIdx.x;
    if (tid < B * 18) {
        int bb = tid / 18, kk = tid % 18;
        double v = 0.0;
        for (int tt = 0; tt < tiles; tt++) v += (double)g_mom_part[bb][tt][kk];
        S[bb][kk] = v;
    }
    __syncthreads();

    if (tid >= B) return;
    int bb = tid;

    double Sw = S[bb][0];
    double invSw = 1.0 / Sw;
    double sp[3] = { S[bb][1], S[bb][2], S[bb][3] };
    double sg[3] = { S[bb][4], S[bb][5], S[bb][6] };

    // Centered cross-covariance in double (cancellation-sensitive step)
    double Md[3][3];
    #pragma unroll
    for (int ii = 0; ii < 3; ii++)
        #pragma unroll
        for (int jj = 0; jj < 3; jj++)
            Md[ii][jj] = S[bb][7 + ii * 3 + jj] - sp[ii] * sg[jj] * invSw;

    // Scale-normalize and drop to float
    double mx = 0.0;
    #pragma unroll
    for (int ii = 0; ii < 3; ii++)
        #pragma unroll
        for (int jj = 0; jj < 3; jj++)
            mx = fmax(mx, fabs(Md[ii][jj]));
    double invmx = (mx > 0.0) ? 1.0 / mx : 0.0;

    float M[3][3];
    #pragma unroll
    for (int ii = 0; ii < 3; ii++)
        #pragma unroll
        for (int jj = 0; jj < 3; jj++)
            M[ii][jj] = (float)(Md[ii][jj] * invmx);

    // A = M^T M (symmetric PSD, entries O(1))
    float A[3][3];
    #pragma unroll
    for (int ii = 0; ii < 3; ii++)
        #pragma unroll
        for (int jj = 0; jj < 3; jj++)
            A[ii][jj] = M[0][ii] * M[0][jj] + M[1][ii] * M[1][jj] + M[2][ii] * M[2][jj];

    float V[3][3] = {{1, 0, 0}, {0, 1, 0}, {0, 0, 1}};

    // Cyclic Jacobi in float (fixed count -> deterministic)
    for (int sweep = 0; sweep < 10; sweep++) {
        #pragma unroll
        for (int pair = 0; pair < 3; pair++) {
            int pp = (pair == 2) ? 1 : 0;
            int qq = (pair == 0) ? 1 : 2;
            float apq = A[pp][qq];
            if (fabsf(apq) < 1e-20f) continue;
            float theta = (A[qq][qq] - A[pp][pp]) / (2.0f * apq);
            float tt2 = ((theta >= 0.0f) ? 1.0f : -1.0f) /
                        (fabsf(theta) + fsqrt_fast(fmaf(theta, theta, 1.0f)));
            float c = rsqrtf(fmaf(tt2, tt2, 1.0f));
            float s = tt2 * c;
            float app = A[pp][pp], aq2 = A[qq][qq];
            A[pp][pp] = app - tt2 * apq;
            A[qq][qq] = aq2 + tt2 * apq;
            A[pp][qq] = A[qq][pp] = 0.0f;
            int r = 3 - pp - qq;
            float arp = A[r][pp], arq = A[r][qq];
            A[r][pp] = A[pp][r] = c * arp - s * arq;
            A[r][qq] = A[qq][r] = s * arp + c * arq;
            #pragma unroll
            for (int kk = 0; kk < 3; kk++) {
                float vkp = V[kk][pp], vkq = V[kk][qq];
                V[kk][pp] = c * vkp - s * vkq;
                V[kk][qq] = s * vkp + c * vkq;
            }
        }
    }

    // Sort eigenvalues descending
    float lam[3] = { A[0][0], A[1][1], A[2][2] };
    int id[3] = {0, 1, 2};
    if (lam[id[0]] < lam[id[1]]) { int x = id[0]; id[0] = id[1]; id[1] = x; }
    if (lam[id[0]] < lam[id[2]]) { int x = id[0]; id[0] = id[2]; id[2] = x; }
    if (lam[id[1]] < lam[id[2]]) { int x = id[1]; id[1] = id[2]; id[2] = x; }

    // U columns: u_k = normalize(M v_k), k=0,1; u_2 = u_0 x u_1 (det flip absorbed)
    float U[3][3];
    #pragma unroll
    for (int kk = 0; kk < 2; kk++) {
        float v0 = V[0][id[kk]], v1 = V[1][id[kk]], v2 = V[2][id[kk]];
        float u0 = M[0][0] * v0 + M[0][1] * v1 + M[0][2] * v2;
        float u1 = M[1][0] * v0 + M[1][1] * v1 + M[1][2] * v2;
        float u2 = M[2][0] * v0 + M[2][1] * v1 + M[2][2] * v2;
        float inv = rsqrtf(fmaxf(u0 * u0 + u1 * u1 + u2 * u2, 1e-30f));
        U[0][kk] = u0 * inv; U[1][kk] = u1 * inv; U[2][kk] = u2 * inv;
    }
    U[0][2] = U[1][0] * U[2][1] - U[2][0] * U[1][1];
    U[1][2] = U[2][0] * U[0][1] - U[0][0] * U[2][1];
    U[2][2] = U[0][0] * U[1][1] - U[1][0] * U[0][1];

    #pragma unroll
    for (int ii = 0; ii < 3; ii++)
        #pragma unroll
        for (int jj = 0; jj < 3; jj++)
            g_R[bb][ii * 3 + jj] = U[ii][0] * V[jj][id[0]] + U[ii][1] * V[jj][id[1]]
                                 + U[ii][2] * V[jj][id[2]];

    #pragma unroll
    for (int ii = 0; ii < 3; ii++) {
        g_mup[bb][ii] = (float)(sp[ii] * invSw);
        g_mug[bb][ii] = (float)(sg[ii] * invSw);
    }

    g_Sw[bb] = Sw;
    g_analytic[bb] = 2.0 * Sw * (S[bb][16] + S[bb][17])
                   - 2.0 * (sp[0] * sp[0] + sp[1] * sp[1] + sp[2] * sp[2]
                          + sg[0] * sg[0] + sg[1] * sg[1] + sg[2] * sg[2]);
}

// ============ Phase 3: point loss + final combine (COLD PATH, noinline) ============
__device__ __noinline__ void pts_phase(
        const float* __restrict__ p, const float* __restrict__ gt,
        const float* __restrict__ w, const float* __restrict__ ht,
        float* __restrict__ out,
        int N, int B, int ncross, int chunks, int cpb, int outn, int fid) {
    int tid = threadIdx.x;
    int pb_ = fid / cpb;
    int i0  = (fid % cpb) * JT;
    const size_t pbase = (size_t)pb_ * N;

    float r00 = g_R[pb_][0], r01 = g_R[pb_][1], r02 = g_R[pb_][2];
    float r10 = g_R[pb_][3], r11 = g_R[pb_][4], r12 = g_R[pb_][5];
    float r20 = g_R[pb_][6], r21 = g_R[pb_][7], r22 = g_R[pb_][8];
    float m0 = g_mup[pb_][0], m1 = g_mup[pb_][1], m2 = g_mup[pb_][2];
    float u0 = g_mug[pb_][0], u1 = g_mug[pb_][1], u2 = g_mug[pb_][2];

    float acc3 = 0.0f;
    int ii = i0 + tid;
    if (ii < N) {
        const float* gb2 = gt + (pbase + ii) * 3;
        const float* pb2 = p  + (pbase + ii) * 3;
        float gx = gb2[0] - u0;
        float gy = gb2[1] - u1;
        float gz = gb2[2] - u2;
        float ax = fmaf(r00, gx, fmaf(r01, gy, r02 * gz)) + m0;
        float ay = fmaf(r10, gx, fmaf(r11, gy, r12 * gz)) + m1;
        float az = fmaf(r20, gx, fmaf(r21, gy, r22 * gz)) + m2;
        float dx = pb2[0] - ax;
        float dy = pb2[1] - ay;
        float dz = pb2[2] - az;
        float nsq = fmaf(dx, dx, fmaf(dy, dy, dz * dz));
        acc3 = w[pbase + ii] * fsqrt_fast(nsq);
    }
    __syncthreads();                // protect reduce scratch reuse
    float tot3 = block_reduce_f(acc3);

    __shared__ int sLast2;
    if (tid == 0) {
        g_pts_part[fid] = tot3;
        __threadfence();
        int old = atomicAdd(&g_count2, 1);
        sLast2 = (old == chunks - 1) ? 1 : 0;
    }
    __syncthreads();
    if (!sLast2) return;

    // ---- final combine (exactly one block; fixed summation order) ----
    double vp = 0.0, vc = 0.0;
    for (int idx = tid; idx < chunks; idx += JT) vp += (double)g_pts_part[idx];
    for (int idx = tid; idx < ncross; idx += JT) vc += (double)g_cross_part[idx];

    __shared__ double rp[JT];
    __shared__ double rc[JT];
    rp[tid] = vp;
    rc[tid] = vc;
    __syncthreads();
    for (int off = JT / 2; off > 0; off >>= 1) {
        if (tid < off) {
            rp[tid] += rp[tid + off];
            rc[tid] += rc[tid + off];
        }
        __syncthreads();
    }

    __shared__ double loss_sh;
    if (tid == 0) {
        double totW = 0.0, den = 0.0, an = 0.0;
        for (int bb = 0; bb < B; bb++) {
            double s = g_Sw[bb];
            totW += s;
            den  += s * s;
            an   += g_analytic[bb];
        }
        double loss_pts  = rp[0] / totW;
        double loss_bond = (an - 2.0 * rc[0]) / den;
        loss_sh = loss_pts + 1.0 * loss_bond;   // ALPHA_BOND = 1
        // self-reset for next graph replay
        g_count1 = 0;
        g_count2 = 0;
        g_flag   = 0;
    }
    __syncthreads();
    int bb = tid;
    if (bb < outn && bb < B) {
        double h = (double)ht[bb];
        out[bb] = (float)((h * h + 256.0) / ((h + 16.0) * (h + 16.0)) * loss_sh);
    }
}

// ================= SINGLE FUSED KERNEL =================
// Phase 1 (all blocks): bond cross tiles (+ moments on diagonal tiles).
// Phase 2 (last phase-1 block): solve_phase(), release flag.
// Phase 3 (blocks with flat id < chunks): pts_phase() after flag.
// Progress guarantee: only <=64 blocks ever spin; >=1184 resident block slots
// exist (launch_bounds min 8 blocks/SM x 148 SMs), so phase-1 blocks always
// make progress; the flag is released only after ALL phase-1 blocks complete.
__global__ void __launch_bounds__(JT, 8) fused_kernel(
        const float* __restrict__ p, const float* __restrict__ gt,
        const float* __restrict__ w, const float* __restrict__ ht,
        float* __restrict__ out,
        int N, int B, int ntri, int tiles, int nblocks, int chunks, int cpb, int outn) {
    // packed-lane shared: group g covers j-pair (2g, 2g+1)
    __shared__ ulonglong2 shPa[JG];           // (px2, py2)   lanes = -2*p
    __shared__ ulonglong2 shPb[JG];           // (pz2, pw2)   pw = |p|^2
    __shared__ ulonglong2 shGa[JG];           // (gx2, gy2)   lanes = -2*g
    __shared__ ulonglong2 shGb[JG];           // (gz2, gw2)   gw = |g|^2
    __shared__ unsigned long long shw[JG];    // (w0, w1)
    __shared__ float smom[4][18];
    __shared__ int   sLast;

    int b   = blockIdx.z;
    int sub = blockIdx.y;
    int k   = blockIdx.x;
    int tid = threadIdx.x;
    // decode triangular index (k uniform per block)
    int ti = (int)((__fsqrt_rn(8.0f * (float)k + 1.0f) - 1.0f) * 0.5f);
    while ((ti + 1) * (ti + 2) / 2 <= k) ti++;
    while (ti * (ti + 1) / 2 > k) ti--;
    int tj = k - ti * (ti + 1) / 2;

    const size_t base = (size_t)b * N;

    // ---- stage the 64-j half-tile as packed lanes (3 thread groups of 32) ----
    {
        int grp = tid & 31;
        int j0 = tj * JT + sub * JH + 2 * grp;
        int j1 = j0 + 1;
        if (tid < 32) {
            float x0 = 0.f, y0 = 0.f, z0 = 0.f, x1 = 0.f, y1 = 0.f, z1 = 0.f;
            if (j0 < N) { const float* q = p + (base + j0) * 3; x0 = q[0]; y0 = q[1]; z0 = q[2]; }
            if (j1 < N) { const float* q = p + (base + j1) * 3; x1 = q[0]; y1 = q[1]; z1 = q[2]; }
            float n0 = fmaf(x0, x0, fmaf(y0, y0, z0 * z0));
            float n1 = fmaf(x1, x1, fmaf(y1, y1, z1 * z1));
            shPa[grp] = make_ulonglong2(packf2(-2.f * x0, -2.f * x1),
                                        packf2(-2.f * y0, -2.f * y1));
            shPb[grp] = make_ulonglong2(packf2(-2.f * z0, -2.f * z1),
                                        packf2(n0, n1));
        } else if (tid < 64) {
            float x0 = 0.f, y0 = 0.f, z0 = 0.f, x1 = 0.f, y1 = 0.f, z1 = 0.f;
            if (j0 < N) { const float* q = gt + (base + j0) * 3; x0 = q[0]; y0 = q[1]; z0 = q[2]; }
            if (j1 < N) { const float* q = gt + (base + j1) * 3; x1 = q[0]; y1 = q[1]; z1 = q[2]; }
            float n0 = fmaf(x0, x0, fmaf(y0, y0, z0 * z0));
            float n1 = fmaf(x1, x1, fmaf(y1, y1, z1 * z1));
            shGa[grp] = make_ulonglong2(packf2(-2.f * x0, -2.f * x1),
                                        packf2(-2.f * y0, -2.f * y1));
            shGb[grp] = make_ulonglong2(packf2(-2.f * z0, -2.f * z1),
                                        packf2(n0, n1));
        } else if (tid < 96) {
            float w0 = (j0 < N) ? w[base + j0] : 0.f;   // w=0 -> no contribution
            float w1 = (j1 < N) ? w[base + j1] : 0.f;
            shw[grp] = packf2(w0, w1);
        }
    }

    int i = ti * JT + tid;
    float xi = 0.f, yi = 0.f, zi = 0.f, gxi = 0.f, gyi = 0.f, gzi = 0.f, wi = 0.f;
    if (i < N) {
        const float* pi = p  + (base + i) * 3;
        const float* gi = gt + (base + i) * 3;
        xi = pi[0]; yi = pi[1]; zi = pi[2];
        gxi = gi[0]; gyi = gi[1]; gzi = gi[2];
        wi = w[base + i];
    }
    float spi = fmaf(xi, xi, fmaf(yi, yi, zi * zi));
    float sgi = fmaf(gxi, gxi, fmaf(gyi, gyi, gzi * gzi));

    // broadcast i-point into packed lanes
    unsigned long long xi2  = packf2(xi, xi),   yi2  = packf2(yi, yi),   zi2  = packf2(zi, zi);
    unsigned long long gxi2 = packf2(gxi, gxi), gyi2 = packf2(gyi, gyi), gzi2 = packf2(gzi, gzi);
    unsigned long long spi2 = packf2(spi, spi), sgi2 = packf2(sgi, sgi);
    __syncthreads();

    unsigned long long acc2 = 0ULL;
    #pragma unroll 8
    for (int jj = 0; jj < JG; jj++) {
        ulonglong2 Pa = shPa[jj];
        ulonglong2 Pb = shPb[jj];
        unsigned long long t;
        ADD2(t, spi2, Pb.y);          // spi + |pj|^2   (both lanes)
        FMA2(t, Pa.x, xi2, t);        // -2 px*xi
        FMA2(t, Pa.y, yi2, t);
        FMA2(t, Pb.x, zi2, t);        // t = dp^2 pair
        ulonglong2 Ga = shGa[jj];
        ulonglong2 Gb = shGb[jj];
        unsigned long long u;
        ADD2(u, sgi2, Gb.y);
        FMA2(u, Ga.x, gxi2, u);
        FMA2(u, Ga.y, gyi2, u);
        FMA2(u, Gb.x, gzi2, u);       // u = dg^2 pair
        unsigned long long prod;
        MUL2(prod, t, u);
        float p0, p1;
        unpackf2(p0, p1, prod);
        float s0 = fsqrt_fast(fmaxf(p0, 0.f));   // dp*dg with ONE sqrt per pair
        float s1 = fsqrt_fast(fmaxf(p1, 0.f));
        unsigned long long s2 = packf2(s0, s1);
        FMA2(acc2, shw[jj], s2, acc2);
    }
    float a0, a1;
    unpackf2(a0, a1, acc2);
    float factor = (ti == tj) ? 1.0f : 2.0f;
    float acc = (a0 + a1) * (wi * factor);

    float tot = block_reduce_f(acc);
    if (tid == 0) g_cross_part[(b * ntri + k) * SPLIT + sub] = tot;

    // Diagonal tiles (one split only) also compute the 18 weighted moments for
    // their i-range (one point per thread, already resident in registers).
    if (ti == tj && sub == 0) {
        float m[18];
        float wpx = wi * xi, wpy = wi * yi, wpz = wi * zi;
        m[0]  = wi;
        m[1]  = wpx; m[2]  = wpy; m[3]  = wpz;
        m[4]  = wi * gxi; m[5]  = wi * gyi; m[6]  = wi * gzi;
        m[7]  = wpx * gxi; m[8]  = wpx * gyi; m[9]  = wpx * gzi;
        m[10] = wpy * gxi; m[11] = wpy * gyi; m[12] = wpy * gzi;
        m[13] = wpz * gxi; m[14] = wpz * gyi; m[15] = wpz * gzi;
        m[16] = wi * spi;
        m[17] = wi * sgi;

        #pragma unroll
        for (int kk = 0; kk < 18; kk++) {
            #pragma unroll
            for (int o = 16; o > 0; o >>= 1)
                m[kk] += __shfl_down_sync(0xffffffffu, m[kk], o);
        }
        int lane = tid & 31, wd = tid >> 5;
        if (lane == 0) {
            #pragma unroll
            for (int kk = 0; kk < 18; kk++) smom[wd][kk] = m[kk];
        }
        __syncthreads();
        if (tid < 18)
            g_mom_part[b][ti][tid] =
                smom[0][tid] + smom[1][tid] + smom[2][tid] + smom[3][tid];
    }

    // ---- phase-1 completion barrier (arrival only) ----
    __syncthreads();
    if (tid == 0) {
        __threadfence();
        int old = atomicAdd(&g_count1, 1);
        sLast = (old == nblocks - 1) ? 1 : 0;
    }
    __syncthreads();

    // ================= Phase 2: solve (last phase-1 block only) =================
    if (sLast) {
        solve_phase(B, tiles);
        __syncthreads();
        if (tid == 0) {
            __threadfence();
            atomicExch(&g_flag, 1);    // release: solve results visible
        }
    }

    // ================= Phase 3: point loss + final combine =================
    int fid = blockIdx.x + gridDim.x * (blockIdx.y + gridDim.y * blockIdx.z);
    if (fid >= chunks) return;        // non-pts blocks exit (never spin)

    if (!sLast) {
        if (tid == 0) {
            while (atomicAdd(&g_flag, 0) == 0) __nanosleep(64);
        }
        __syncthreads();
        __threadfence();
    }

    pts_phase(p, gt, w, ht, out, N, B, nblocks, chunks, cpb, outn, fid);
}

// ---------------- launcher ----------------
extern "C" void kernel_launch(void* const* d_in, const int* in_sizes, int n_in,
                              void* d_out, int out_size) {
    const float* p  = (const float*)d_in[0];  // xpred_l [B,N,3]
    const float* g  = (const float*)d_in[1];  // xGT_l   [B,N,3]
    const float* ht = (const float*)d_in[2];  // ht      [B]
    const float* w  = (const float*)d_in[3];  // w_l     [B,N]

    int B = in_sizes[2];
    if (B > MAXB) B = MAXB;
    int N = in_sizes[3] / B;

    int tiles = (N + JT - 1) / JT;
    if (tiles > MAXTILES) tiles = MAXTILES;   // (inputs are B=4, N=2048 -> 16 tiles)
    int ntri = tiles * (tiles + 1) / 2;
    int nblocks = ntri * SPLIT * B;
    int cpb = (N + JT - 1) / JT;
    int chunks = B * cpb;

    fused_kernel<<<dim3(ntri, SPLIT, B), JT>>>(p, g, w, ht, (float*)d_out,
                                               N, B, ntri, tiles, nblocks,
                                               chunks, cpb, out_size);
}

// round 14
// speedup vs baseline: 1.0817x; 1.0651x over previous
#include <cuda_runtime.h>
#include <cstdint>

#define MAXB 8
#define JT 128
#define SPLIT 2
#define JH (JT / SPLIT)
#define JG (JH / 2)          // packed j-groups per block
#define MAXTILES 40
#define MAXTRI (MAXTILES * (MAXTILES + 1) / 2)   // 820

// ---------------- scratch (device globals; no allocation) ----------------
__device__ float  g_mom_part[MAXB][MAXTILES][18];       // per-diagonal-tile moment partials
__device__ float  g_cross_part[MAXB * MAXTRI * SPLIT];  // per-block bond cross partials
__device__ float  g_pts_part[MAXB * MAXTILES];          // per-chunk point-loss partials
__device__ double g_Sw[MAXB];
__device__ double g_analytic[MAXB];
__device__ float  g_R[MAXB][9];
__device__ float  g_mup[MAXB][3];
__device__ float  g_mug[MAXB][3];
__device__ int    g_count1 = 0;    // phase-1 completion counter (self-resetting)
__device__ int    g_count2 = 0;    // pts completion counter (self-resetting)
__device__ int    g_flag   = 0;    // solve-done flag (self-resetting)

// ---- packed f32x2 helpers (sm_103a FFMA2 path) ----
#define FMA2(d, a, b, c) asm("fma.rn.f32x2 %0, %1, %2, %3;" : "=l"(d) : "l"(a), "l"(b), "l"(c))
#define ADD2(d, a, b)    asm("add.rn.f32x2 %0, %1, %2;"     : "=l"(d) : "l"(a), "l"(b))
#define MUL2(d, a, b)    asm("mul.rn.f32x2 %0, %1, %2;"     : "=l"(d) : "l"(a), "l"(b))

__device__ __forceinline__ unsigned long long packf2(float lo, float hi) {
    unsigned long long r;
    asm("mov.b64 %0, {%1, %2};" : "=l"(r) : "f"(lo), "f"(hi));
    return r;
}
__device__ __forceinline__ void unpackf2(float& lo, float& hi, unsigned long long v) {
    asm("mov.b64 {%0, %1}, %2;" : "=f"(lo), "=f"(hi) : "l"(v));
}

__device__ __forceinline__ float fsqrt_fast(float x) {
    float r; asm("sqrt.approx.f32 %0, %1;" : "=f"(r) : "f"(x)); return r;
}

__device__ __forceinline__ float block_reduce_f(float v) {
    #pragma unroll
    for (int o = 16; o > 0; o >>= 1) v += __shfl_down_sync(0xffffffffu, v, o);
    __shared__ float s[32];
    int lane = threadIdx.x & 31, wid = threadIdx.x >> 5;
    if (lane == 0) s[wid] = v;
    __syncthreads();
    int nw = (blockDim.x + 31) >> 5;
    v = (threadIdx.x < nw) ? s[threadIdx.x] : 0.0f;
    if (wid == 0) {
        #pragma unroll
        for (int o = 16; o > 0; o >>= 1) v += __shfl_down_sync(0xffffffffu, v, o);
    }
    return v;  // valid in thread 0
}

// ============ Phase 2: moment combine + Kabsch solve (COLD PATH, noinline) ============
__device__ __noinline__ void solve_phase(int B, int tiles) {
    __shared__ double S[MAXB][18];
    int tid = threadIdx.x;
    if (tid < B * 18) {
        int bb = tid / 18, kk = tid % 18;
        double v = 0.0;
        for (int tt = 0; tt < tiles; tt++) v += (double)g_mom_part[bb][tt][kk];
        S[bb][kk] = v;
    }
    __syncthreads();

    if (tid >= B) return;
    int bb = tid;

    double Sw = S[bb][0];
    double invSw = 1.0 / Sw;
    double sp[3] = { S[bb][1], S[bb][2], S[bb][3] };
    double sg[3] = { S[bb][4], S[bb][5], S[bb][6] };

    // Centered cross-covariance in double (cancellation-sensitive step)
    double Md[3][3];
    #pragma unroll
    for (int ii = 0; ii < 3; ii++)
        #pragma unroll
        for (int jj = 0; jj < 3; jj++)
            Md[ii][jj] = S[bb][7 + ii * 3 + jj] - sp[ii] * sg[jj] * invSw;

    // Scale-normalize and drop to float
    double mx = 0.0;
    #pragma unroll
    for (int ii = 0; ii < 3; ii++)
        #pragma unroll
        for (int jj = 0; jj < 3; jj++)
            mx = fmax(mx, fabs(Md[ii][jj]));
    double invmx = (mx > 0.0) ? 1.0 / mx : 0.0;

    float M[3][3];
    #pragma unroll
    for (int ii = 0; ii < 3; ii++)
        #pragma unroll
        for (int jj = 0; jj < 3; jj++)
            M[ii][jj] = (float)(Md[ii][jj] * invmx);

    // A = M^T M (symmetric PSD, entries O(1))
    float A[3][3];
    #pragma unroll
    for (int ii = 0; ii < 3; ii++)
        #pragma unroll
        for (int jj = 0; jj < 3; jj++)
            A[ii][jj] = M[0][ii] * M[0][jj] + M[1][ii] * M[1][jj] + M[2][ii] * M[2][jj];

    float V[3][3] = {{1, 0, 0}, {0, 1, 0}, {0, 0, 1}};

    // Cyclic Jacobi in float (fixed count -> deterministic)
    for (int sweep = 0; sweep < 10; sweep++) {
        #pragma unroll
        for (int pair = 0; pair < 3; pair++) {
            int pp = (pair == 2) ? 1 : 0;
            int qq = (pair == 0) ? 1 : 2;
            float apq = A[pp][qq];
            if (fabsf(apq) < 1e-20f) continue;
            float theta = (A[qq][qq] - A[pp][pp]) / (2.0f * apq);
            float tt2 = ((theta >= 0.0f) ? 1.0f : -1.0f) /
                        (fabsf(theta) + fsqrt_fast(fmaf(theta, theta, 1.0f)));
            float c = rsqrtf(fmaf(tt2, tt2, 1.0f));
            float s = tt2 * c;
            float app = A[pp][pp], aq2 = A[qq][qq];
            A[pp][pp] = app - tt2 * apq;
            A[qq][qq] = aq2 + tt2 * apq;
            A[pp][qq] = A[qq][pp] = 0.0f;
            int r = 3 - pp - qq;
            float arp = A[r][pp], arq = A[r][qq];
            A[r][pp] = A[pp][r] = c * arp - s * arq;
            A[r][qq] = A[qq][r] = s * arp + c * arq;
            #pragma unroll
            for (int kk = 0; kk < 3; kk++) {
                float vkp = V[kk][pp], vkq = V[kk][qq];
                V[kk][pp] = c * vkp - s * vkq;
                V[kk][qq] = s * vkp + c * vkq;
            }
        }
    }

    // Sort eigenvalues descending
    float lam[3] = { A[0][0], A[1][1], A[2][2] };
    int id[3] = {0, 1, 2};
    if (lam[id[0]] < lam[id[1]]) { int x = id[0]; id[0] = id[1]; id[1] = x; }
    if (lam[id[0]] < lam[id[2]]) { int x = id[0]; id[0] = id[2]; id[2] = x; }
    if (lam[id[1]] < lam[id[2]]) { int x = id[1]; id[1] = id[2]; id[2] = x; }

    // U columns: u_k = normalize(M v_k), k=0,1; u_2 = u_0 x u_1 (det flip absorbed)
    float U[3][3];
    #pragma unroll
    for (int kk = 0; kk < 2; kk++) {
        float v0 = V[0][id[kk]], v1 = V[1][id[kk]], v2 = V[2][id[kk]];
        float u0 = M[0][0] * v0 + M[0][1] * v1 + M[0][2] * v2;
        float u1 = M[1][0] * v0 + M[1][1] * v1 + M[1][2] * v2;
        float u2 = M[2][0] * v0 + M[2][1] * v1 + M[2][2] * v2;
        float inv = rsqrtf(fmaxf(u0 * u0 + u1 * u1 + u2 * u2, 1e-30f));
        U[0][kk] = u0 * inv; U[1][kk] = u1 * inv; U[2][kk] = u2 * inv;
    }
    U[0][2] = U[1][0] * U[2][1] - U[2][0] * U[1][1];
    U[1][2] = U[2][0] * U[0][1] - U[0][0] * U[2][1];
    U[2][2] = U[0][0] * U[1][1] - U[1][0] * U[0][1];

    #pragma unroll
    for (int ii = 0; ii < 3; ii++)
        #pragma unroll
        for (int jj = 0; jj < 3; jj++)
            g_R[bb][ii * 3 + jj] = U[ii][0] * V[jj][id[0]] + U[ii][1] * V[jj][id[1]]
                                 + U[ii][2] * V[jj][id[2]];

    #pragma unroll
    for (int ii = 0; ii < 3; ii++) {
        g_mup[bb][ii] = (float)(sp[ii] * invSw);
        g_mug[bb][ii] = (float)(sg[ii] * invSw);
    }

    g_Sw[bb] = Sw;
    g_analytic[bb] = 2.0 * Sw * (S[bb][16] + S[bb][17])
                   - 2.0 * (sp[0] * sp[0] + sp[1] * sp[1] + sp[2] * sp[2]
                          + sg[0] * sg[0] + sg[1] * sg[1] + sg[2] * sg[2]);
}

// ============ Phase 3: point loss + final combine (COLD PATH, noinline) ============
__device__ __noinline__ void pts_phase(
        const float* __restrict__ p, const float* __restrict__ gt,
        const float* __restrict__ w, const float* __restrict__ ht,
        float* __restrict__ out,
        int N, int B, int ncross, int chunks, int cpb, int outn, int fid) {
    int tid = threadIdx.x;
    int pb_ = fid / cpb;
    int i0  = (fid % cpb) * JT;
    const size_t pbase = (size_t)pb_ * N;

    float r00 = g_R[pb_][0], r01 = g_R[pb_][1], r02 = g_R[pb_][2];
    float r10 = g_R[pb_][3], r11 = g_R[pb_][4], r12 = g_R[pb_][5];
    float r20 = g_R[pb_][6], r21 = g_R[pb_][7], r22 = g_R[pb_][8];
    float m0 = g_mup[pb_][0], m1 = g_mup[pb_][1], m2 = g_mup[pb_][2];
    float u0 = g_mug[pb_][0], u1 = g_mug[pb_][1], u2 = g_mug[pb_][2];

    float acc3 = 0.0f;
    int ii = i0 + tid;
    if (ii < N) {
        const float* gb2 = gt + (pbase + ii) * 3;
        const float* pb2 = p  + (pbase + ii) * 3;
        float gx = gb2[0] - u0;
        float gy = gb2[1] - u1;
        float gz = gb2[2] - u2;
        float ax = fmaf(r00, gx, fmaf(r01, gy, r02 * gz)) + m0;
        float ay = fmaf(r10, gx, fmaf(r11, gy, r12 * gz)) + m1;
        float az = fmaf(r20, gx, fmaf(r21, gy, r22 * gz)) + m2;
        float dx = pb2[0] - ax;
        float dy = pb2[1] - ay;
        float dz = pb2[2] - az;
        float nsq = fmaf(dx, dx, fmaf(dy, dy, dz * dz));
        acc3 = w[pbase + ii] * fsqrt_fast(nsq);
    }
    __syncthreads();                // protect reduce scratch reuse
    float tot3 = block_reduce_f(acc3);

    __shared__ int sLast2;
    if (tid == 0) {
        g_pts_part[fid] = tot3;
        __threadfence();
        int old = atomicAdd(&g_count2, 1);
        sLast2 = (old == chunks - 1) ? 1 : 0;
    }
    __syncthreads();
    if (!sLast2) return;

    // ---- final combine (exactly one block; fixed summation order) ----
    double vp = 0.0, vc = 0.0;
    for (int idx = tid; idx < chunks; idx += JT) vp += (double)g_pts_part[idx];
    for (int idx = tid; idx < ncross; idx += JT) vc += (double)g_cross_part[idx];

    __shared__ double rp[JT];
    __shared__ double rc[JT];
    rp[tid] = vp;
    rc[tid] = vc;
    __syncthreads();
    for (int off = JT / 2; off > 0; off >>= 1) {
        if (tid < off) {
            rp[tid] += rp[tid + off];
            rc[tid] += rc[tid + off];
        }
        __syncthreads();
    }

    __shared__ double loss_sh;
    if (tid == 0) {
        double totW = 0.0, den = 0.0, an = 0.0;
        for (int bb = 0; bb < B; bb++) {
            double s = g_Sw[bb];
            totW += s;
            den  += s * s;
            an   += g_analytic[bb];
        }
        double loss_pts  = rp[0] / totW;
        double loss_bond = (an - 2.0 * rc[0]) / den;
        loss_sh = loss_pts + 1.0 * loss_bond;   // ALPHA_BOND = 1
        // self-reset for next graph replay
        g_count1 = 0;
        g_count2 = 0;
        g_flag   = 0;
    }
    __syncthreads();
    int bb = tid;
    if (bb < outn && bb < B) {
        double h = (double)ht[bb];
        out[bb] = (float)((h * h + 256.0) / ((h + 16.0) * (h + 16.0)) * loss_sh);
    }
}

// ================= SINGLE FUSED KERNEL =================
// Phase 1 (all blocks): bond cross tiles (+ moments on diagonal tiles).
// Phase 2 (last phase-1 block): solve_phase(), release flag.
// Phase 3 (blocks with flat id < chunks): pts_phase() after flag.
// Progress guarantee: only <=64 blocks ever spin; >=1184 resident block slots
// exist (launch_bounds min 8 blocks/SM x 148 SMs), so phase-1 blocks always
// make progress; the flag is released only after ALL phase-1 blocks complete.
__global__ void __launch_bounds__(JT, 8) fused_kernel(
        const float* __restrict__ p, const float* __restrict__ gt,
        const float* __restrict__ w, const float* __restrict__ ht,
        float* __restrict__ out,
        int N, int B, int ntri, int tiles, int nblocks, int chunks, int cpb, int outn) {
    // packed-lane shared: group g covers j-pair (2g, 2g+1)
    __shared__ ulonglong2 shPa[JG];           // (px2, py2)   lanes = -2*p
    __shared__ ulonglong2 shPb[JG];           // (pz2, pw2)   pw = |p|^2
    __shared__ ulonglong2 shGa[JG];           // (gx2, gy2)   lanes = -2*g
    __shared__ ulonglong2 shGb[JG];           // (gz2, gw2)   gw = |g|^2
    __shared__ unsigned long long shw[JG];    // (w0, w1)
    __shared__ float smom[4][18];
    __shared__ int   sLast;

    int b   = blockIdx.z;
    int sub = blockIdx.y;
    int k   = blockIdx.x;
    int tid = threadIdx.x;
    // decode triangular index (k uniform per block)
    int ti = (int)((__fsqrt_rn(8.0f * (float)k + 1.0f) - 1.0f) * 0.5f);
    while ((ti + 1) * (ti + 2) / 2 <= k) ti++;
    while (ti * (ti + 1) / 2 > k) ti--;
    int tj = k - ti * (ti + 1) / 2;

    const size_t base = (size_t)b * N;

    // ---- stage the 64-j half-tile as packed lanes (3 thread groups of 32) ----
    {
        int grp = tid & 31;
        int j0 = tj * JT + sub * JH + 2 * grp;
        int j1 = j0 + 1;
        if (tid < 32) {
            float x0 = 0.f, y0 = 0.f, z0 = 0.f, x1 = 0.f, y1 = 0.f, z1 = 0.f;
            if (j0 < N) { const float* q = p + (base + j0) * 3; x0 = q[0]; y0 = q[1]; z0 = q[2]; }
            if (j1 < N) { const float* q = p + (base + j1) * 3; x1 = q[0]; y1 = q[1]; z1 = q[2]; }
            float n0 = fmaf(x0, x0, fmaf(y0, y0, z0 * z0));
            float n1 = fmaf(x1, x1, fmaf(y1, y1, z1 * z1));
            shPa[grp] = make_ulonglong2(packf2(-2.f * x0, -2.f * x1),
                                        packf2(-2.f * y0, -2.f * y1));
            shPb[grp] = make_ulonglong2(packf2(-2.f * z0, -2.f * z1),
                                        packf2(n0, n1));
        } else if (tid < 64) {
            float x0 = 0.f, y0 = 0.f, z0 = 0.f, x1 = 0.f, y1 = 0.f, z1 = 0.f;
            if (j0 < N) { const float* q = gt + (base + j0) * 3; x0 = q[0]; y0 = q[1]; z0 = q[2]; }
            if (j1 < N) { const float* q = gt + (base + j1) * 3; x1 = q[0]; y1 = q[1]; z1 = q[2]; }
            float n0 = fmaf(x0, x0, fmaf(y0, y0, z0 * z0));
            float n1 = fmaf(x1, x1, fmaf(y1, y1, z1 * z1));
            shGa[grp] = make_ulonglong2(packf2(-2.f * x0, -2.f * x1),
                                        packf2(-2.f * y0, -2.f * y1));
            shGb[grp] = make_ulonglong2(packf2(-2.f * z0, -2.f * z1),
                                        packf2(n0, n1));
        } else if (tid < 96) {
            float w0 = (j0 < N) ? w[base + j0] : 0.f;   // w=0 -> no contribution
            float w1 = (j1 < N) ? w[base + j1] : 0.f;
            shw[grp] = packf2(w0, w1);
        }
    }

    int i = ti * JT + tid;
    float xi = 0.f, yi = 0.f, zi = 0.f, gxi = 0.f, gyi = 0.f, gzi = 0.f, wi = 0.f;
    if (i < N) {
        const float* pi = p  + (base + i) * 3;
        const float* gi = gt + (base + i) * 3;
        xi = pi[0]; yi = pi[1]; zi = pi[2];
        gxi = gi[0]; gyi = gi[1]; gzi = gi[2];
        wi = w[base + i];
    }
    float spi = fmaf(xi, xi, fmaf(yi, yi, zi * zi));
    float sgi = fmaf(gxi, gxi, fmaf(gyi, gyi, gzi * gzi));

    // broadcast i-point into packed lanes
    unsigned long long xi2  = packf2(xi, xi),   yi2  = packf2(yi, yi),   zi2  = packf2(zi, zi);
    unsigned long long gxi2 = packf2(gxi, gxi), gyi2 = packf2(gyi, gyi), gzi2 = packf2(gzi, gzi);
    unsigned long long spi2 = packf2(spi, spi), sgi2 = packf2(sgi, sgi);
    __syncthreads();

    unsigned long long acc2 = 0ULL;
    #pragma unroll 8
    for (int jj = 0; jj < JG; jj++) {
        ulonglong2 Pa = shPa[jj];
        ulonglong2 Pb = shPb[jj];
        unsigned long long t;
        ADD2(t, spi2, Pb.y);          // spi + |pj|^2   (both lanes)
        FMA2(t, Pa.x, xi2, t);        // -2 px*xi
        FMA2(t, Pa.y, yi2, t);
        FMA2(t, Pb.x, zi2, t);        // t = dp^2 pair
        ulonglong2 Ga = shGa[jj];
        ulonglong2 Gb = shGb[jj];
        unsigned long long u;
        ADD2(u, sgi2, Gb.y);
        FMA2(u, Ga.x, gxi2, u);
        FMA2(u, Ga.y, gyi2, u);
        FMA2(u, Gb.x, gzi2, u);       // u = dg^2 pair
        unsigned long long prod;
        MUL2(prod, t, u);
        float p0, p1;
        unpackf2(p0, p1, prod);
        float s0 = fsqrt_fast(fmaxf(p0, 0.f));   // dp*dg with ONE sqrt per pair
        float s1 = fsqrt_fast(fmaxf(p1, 0.f));
        unsigned long long s2 = packf2(s0, s1);
        FMA2(acc2, shw[jj], s2, acc2);
    }
    float a0, a1;
    unpackf2(a0, a1, acc2);
    float factor = (ti == tj) ? 1.0f : 2.0f;
    float acc = (a0 + a1) * (wi * factor);

    float tot = block_reduce_f(acc);
    if (tid == 0) g_cross_part[(b * ntri + k) * SPLIT + sub] = tot;

    // Diagonal tiles (one split only) also compute the 18 weighted moments for
    // their i-range (one point per thread, already resident in registers).
    if (ti == tj && sub == 0) {
        float m[18];
        float wpx = wi * xi, wpy = wi * yi, wpz = wi * zi;
        m[0]  = wi;
        m[1]  = wpx; m[2]  = wpy; m[3]  = wpz;
        m[4]  = wi * gxi; m[5]  = wi * gyi; m[6]  = wi * gzi;
        m[7]  = wpx * gxi; m[8]  = wpx * gyi; m[9]  = wpx * gzi;
        m[10] = wpy * gxi; m[11] = wpy * gyi; m[12] = wpy * gzi;
        m[13] = wpz * gxi; m[14] = wpz * gyi; m[15] = wpz * gzi;
        m[16] = wi * spi;
        m[17] = wi * sgi;

        #pragma unroll
        for (int kk = 0; kk < 18; kk++) {
            #pragma unroll
            for (int o = 16; o > 0; o >>= 1)
                m[kk] += __shfl_down_sync(0xffffffffu, m[kk], o);
        }
        int lane = tid & 31, wd = tid >> 5;
        if (lane == 0) {
            #pragma unroll
            for (int kk = 0; kk < 18; kk++) smom[wd][kk] = m[kk];
        }
        __syncthreads();
        if (tid < 18)
            g_mom_part[b][ti][tid] =
                smom[0][tid] + smom[1][tid] + smom[2][tid] + smom[3][tid];
    }

    // ---- phase-1 completion barrier (arrival only) ----
    __syncthreads();
    if (tid == 0) {
        __threadfence();
        int old = atomicAdd(&g_count1, 1);
        sLast = (old == nblocks - 1) ? 1 : 0;
    }
    __syncthreads();

    // ================= Phase 2: solve (last phase-1 block only) =================
    if (sLast) {
        solve_phase(B, tiles);
        __syncthreads();
        if (tid == 0) {
            __threadfence();
            atomicExch(&g_flag, 1);    // release: solve results visible
        }
    }

    // ================= Phase 3: point loss + final combine =================
    int fid = blockIdx.x + gridDim.x * (blockIdx.y + gridDim.y * blockIdx.z);
    if (fid >= chunks) return;        // non-pts blocks exit (never spin)

    if (!sLast) {
        if (tid == 0) {
            while (atomicAdd(&g_flag, 0) == 0) __nanosleep(64);
        }
        __syncthreads();
        __threadfence();
    }

    pts_phase(p, gt, w, ht, out, N, B, nblocks, chunks, cpb, outn, fid);
}

// ---------------- launcher ----------------
extern "C" void kernel_launch(void* const* d_in, const int* in_sizes, int n_in,
                              void* d_out, int out_size) {
    const float* p  = (const float*)d_in[0];  // xpred_l [B,N,3]
    const float* g  = (const float*)d_in[1];  // xGT_l   [B,N,3]
    const float* ht = (const float*)d_in[2];  // ht      [B]
    const float* w  = (const float*)d_in[3];  // w_l     [B,N]

    int B = in_sizes[2];
    if (B > MAXB) B = MAXB;
    int N = in_sizes[3] / B;

    int tiles = (N + JT - 1) / JT;
    if (tiles > MAXTILES) tiles = MAXTILES;   // (inputs are B=4, N=2048 -> 16 tiles)
    int ntri = tiles * (tiles + 1) / 2;
    int nblocks = ntri * SPLIT * B;
    int cpb = (N + JT - 1) / JT;
    int chunks = B * cpb;

    fused_kernel<<<dim3(ntri, SPLIT, B), JT>>>(p, g, w, ht, (float*)d_out,
                                               N, B, ntri, tiles, nblocks,
                                               chunks, cpb, out_size);
}